// round 5
// baseline (speedup 1.0000x reference)
#include <cuda_runtime.h>
#include <cstdint>

// Problem constants
#define HD  128     // hidden size
#define BBZ 512     // batch
#define LL  1000    // sequence length
#define NB  16      // batch rows per cluster
#define CLN 4       // CTAs per cluster
#define NTHREADS 256

// Shared memory layout (float offsets). Each CTA (cluster rank r) holds the
// weight rows for hidden units [32r, 32r+32) of BOTH layers, stored k-major:
//   Wt[k*128 + (g*32+u)] = W[(g*128 + 32r + u)*128 + k]
#define OFF_W1   0        // w_hh1 slice   [128k][128r]
#define OFF_W2   16384    // w_ih2 slice
#define OFF_W3   32768    // w_hh2 slice
#define OFF_H1   49152    // h1 double buffer [2][NB][HD]  (b-major, k contiguous)
#define OFF_H2   53248    // h2 double buffer [2][NB][HD]
#define OFF_WIH1 57344    // w_ih1 slice [128]
#define OFF_B1   57472    // b_ih1+b_hh1 slice [128]
#define OFF_B2   57600    // b_ih2+b_hh2 slice [128]
#define OFF_WLIN 57728    // w_lin [128]
#define OFF_XS   57856    // x double buffer [2][NB]
#define SMEM_FLOATS 57888
#define SMEM_BYTES (SMEM_FLOATS * 4)   // 231552 B <= 232448 max

__device__ __forceinline__ float sigf(float v) {
    return __fdividef(1.f, 1.f + __expf(-v));
}
__device__ __forceinline__ float tanhf_fast(float v) {
    float a = fabsf(v);
    float e = __expf(-2.f * a);
    float r = __fdividef(1.f - e, 1.f + e);
    return copysignf(r, v);
}
__device__ __forceinline__ void cluster_bar() {
    asm volatile("barrier.cluster.arrive.aligned;" ::: "memory");
    asm volatile("barrier.cluster.wait.aligned;" ::: "memory");
}

__global__ void __launch_bounds__(NTHREADS, 1) __cluster_dims__(CLN, 1, 1)
lstm_persistent_kernel(const float* __restrict__ x,
                       const float* __restrict__ w_ih1,
                       const float* __restrict__ w_hh1,
                       const float* __restrict__ b_ih1,
                       const float* __restrict__ b_hh1,
                       const float* __restrict__ w_ih2,
                       const float* __restrict__ w_hh2,
                       const float* __restrict__ b_ih2,
                       const float* __restrict__ b_hh2,
                       const float* __restrict__ w_lin,
                       const float* __restrict__ b_lin,
                       float* __restrict__ out)
{
    extern __shared__ float sm[];
    const int tid = threadIdx.x;
    uint32_t rank;
    asm("mov.u32 %0, %%cluster_ctarank;" : "=r"(rank));
    const int cid = blockIdx.x / CLN;       // cluster id (0..31)
    const int batch0 = cid * NB;            // global batch base for this cluster

    // ---- init: load + transpose weight slices into smem (coalesced reads) ----
    for (int idx = tid; idx < 128 * HD; idx += NTHREADS) {
        int r = idx / HD, k = idx % HD;
        int g = r >> 5, u = r & 31;
        int R = g * HD + (int)rank * 32 + u;          // global row in [4H]
        sm[OFF_W1 + k * 128 + r] = w_hh1[R * HD + k];
        sm[OFF_W2 + k * 128 + r] = w_ih2[R * HD + k];
        sm[OFF_W3 + k * 128 + r] = w_hh2[R * HD + k];
    }
    if (tid < 128) {
        int g = tid >> 5, u = tid & 31;
        int R = g * HD + (int)rank * 32 + u;
        sm[OFF_WIH1 + tid] = w_ih1[R];
        sm[OFF_B1 + tid]   = b_ih1[R] + b_hh1[R];
        sm[OFF_B2 + tid]   = b_ih2[R] + b_hh2[R];
        sm[OFF_WLIN + tid] = w_lin[tid];
    }
    for (int idx = tid; idx < 2 * NB * HD; idx += NTHREADS) {
        sm[OFF_H1 + idx] = 0.f;
        sm[OFF_H2 + idx] = 0.f;
    }
    if (tid < NB) sm[OFF_XS + tid] = x[(size_t)(batch0 + tid) * LL];
    const float blin = b_lin[0];

    cluster_bar();   // weights/state visible cluster-wide before loop

    // ---- per-thread work assignment: (hidden unit u, batch pair bp) ----
    const int u  = tid & 31;
    const int bp = tid >> 5;          // 0..7
    const int b0 = bp * 2, b1 = b0 + 1;
    const int gu = (int)rank * 32 + u;   // global hidden unit index

    // hoisted per-thread constants
    const float wi0 = sm[OFF_WIH1 + u],      wi1 = sm[OFF_WIH1 + 32 + u];
    const float wi2 = sm[OFF_WIH1 + 64 + u], wi3 = sm[OFF_WIH1 + 96 + u];
    const float bA0 = sm[OFF_B1 + u],        bA1 = sm[OFF_B1 + 32 + u];
    const float bA2 = sm[OFF_B1 + 64 + u],   bA3 = sm[OFF_B1 + 96 + u];
    const float bB0 = sm[OFF_B2 + u],        bB1 = sm[OFF_B2 + 32 + u];
    const float bB2 = sm[OFF_B2 + 64 + u],   bB3 = sm[OFF_B2 + 96 + u];

    float c1s0 = 0.f, c1s1 = 0.f;   // cell state layer1 for b0,b1
    float c2s0 = 0.f, c2s1 = 0.f;   // cell state layer2

    // precompute DSMEM base addresses of all 4 cluster ranks
    uint32_t sbase = (uint32_t)__cvta_generic_to_shared(sm);
    uint32_t peer[CLN];
#pragma unroll
    for (int r = 0; r < CLN; r++) {
        asm("mapa.shared::cluster.u32 %0, %1, %2;" : "=r"(peer[r]) : "r"(sbase), "r"(r));
    }

    for (int t = 0; t < LL; ++t) {
        const int pbuf = t & 1, qbuf = pbuf ^ 1;

        // prefetch x for step t+1 into the other buffer
        if (tid < NB && t + 1 < LL)
            sm[OFF_XS + qbuf * NB + tid] = x[(size_t)(batch0 + tid) * LL + (t + 1)];

        // ---------- layer 1: acc = Whh1_slice @ h1[qbuf] ----------
        float a00 = 0.f, a01 = 0.f, a10 = 0.f, a11 = 0.f;
        float a20 = 0.f, a21 = 0.f, a30 = 0.f, a31 = 0.f;
        {
            const float* __restrict__ wk = sm + OFF_W1 + u;
            const float* __restrict__ ha = sm + OFF_H1 + qbuf * (NB * HD) + b0 * HD;
            const float* __restrict__ hb = ha + HD;
#pragma unroll 8
            for (int k = 0; k < HD; ++k) {
                float w0 = wk[0], w1 = wk[32], w2 = wk[64], w3 = wk[96];
                float h0 = ha[k], h1v = hb[k];
                a00 = fmaf(w0, h0, a00); a01 = fmaf(w0, h1v, a01);
                a10 = fmaf(w1, h0, a10); a11 = fmaf(w1, h1v, a11);
                a20 = fmaf(w2, h0, a20); a21 = fmaf(w2, h1v, a21);
                a30 = fmaf(w3, h0, a30); a31 = fmaf(w3, h1v, a31);
                wk += 128;
            }
        }
        // ---------- layer 1 cell + broadcast h1 slice to cluster ----------
        {
            const float xv0 = sm[OFF_XS + pbuf * NB + b0];
            const float xv1 = sm[OFF_XS + pbuf * NB + b1];

            float pi = fmaf(xv0, wi0, a00) + bA0;
            float pf = fmaf(xv0, wi1, a10) + bA1;
            float pg = fmaf(xv0, wi2, a20) + bA2;
            float po = fmaf(xv0, wi3, a30) + bA3;
            float ig = sigf(pi), fg = sigf(pf), gg = tanhf_fast(pg), og = sigf(po);
            float c = fmaf(fg, c1s0, ig * gg); c1s0 = c;
            float hA = og * tanhf_fast(c);

            pi = fmaf(xv1, wi0, a01) + bA0;
            pf = fmaf(xv1, wi1, a11) + bA1;
            pg = fmaf(xv1, wi2, a21) + bA2;
            po = fmaf(xv1, wi3, a31) + bA3;
            ig = sigf(pi); fg = sigf(pf); gg = tanhf_fast(pg); og = sigf(po);
            c = fmaf(fg, c1s1, ig * gg); c1s1 = c;
            float hB = og * tanhf_fast(c);

            uint32_t offA = (uint32_t)((OFF_H1 + (pbuf * NB + b0) * HD + gu) * 4);
            uint32_t offB = offA + HD * 4;
#pragma unroll
            for (int r = 0; r < CLN; r++) {
                asm volatile("st.shared::cluster.f32 [%0], %1;" :: "r"(peer[r] + offA), "f"(hA) : "memory");
                asm volatile("st.shared::cluster.f32 [%0], %1;" :: "r"(peer[r] + offB), "f"(hB) : "memory");
            }
        }
        cluster_bar();   // h1[pbuf] complete cluster-wide

        // ---------- layer 2: acc = Wih2_slice @ h1[pbuf] + Whh2_slice @ h2[qbuf] ----------
        a00 = 0.f; a01 = 0.f; a10 = 0.f; a11 = 0.f;
        a20 = 0.f; a21 = 0.f; a30 = 0.f; a31 = 0.f;
        {
            const float* __restrict__ wk2 = sm + OFF_W2 + u;
            const float* __restrict__ wk3 = sm + OFF_W3 + u;
            const float* __restrict__ pa = sm + OFF_H1 + pbuf * (NB * HD) + b0 * HD;
            const float* __restrict__ pbv = pa + HD;
            const float* __restrict__ qa = sm + OFF_H2 + qbuf * (NB * HD) + b0 * HD;
            const float* __restrict__ qbv = qa + HD;
#pragma unroll 4
            for (int k = 0; k < HD; ++k) {
                float h0 = pa[k], h1v = pbv[k];
                float g0 = qa[k], g1 = qbv[k];
                float w0 = wk2[0], w1 = wk2[32], w2 = wk2[64], w3 = wk2[96];
                a00 = fmaf(w0, h0, a00); a01 = fmaf(w0, h1v, a01);
                a10 = fmaf(w1, h0, a10); a11 = fmaf(w1, h1v, a11);
                a20 = fmaf(w2, h0, a20); a21 = fmaf(w2, h1v, a21);
                a30 = fmaf(w3, h0, a30); a31 = fmaf(w3, h1v, a31);
                float v0 = wk3[0], v1 = wk3[32], v2 = wk3[64], v3 = wk3[96];
                a00 = fmaf(v0, g0, a00); a01 = fmaf(v0, g1, a01);
                a10 = fmaf(v1, g0, a10); a11 = fmaf(v1, g1, a11);
                a20 = fmaf(v2, g0, a20); a21 = fmaf(v2, g1, a21);
                a30 = fmaf(v3, g0, a30); a31 = fmaf(v3, g1, a31);
                wk2 += 128; wk3 += 128;
            }
        }
        // ---------- layer 2 cell + broadcast h2 slice ----------
        {
            float pi = a00 + bB0;
            float pf = a10 + bB1;
            float pg = a20 + bB2;
            float po = a30 + bB3;
            float ig = sigf(pi), fg = sigf(pf), gg = tanhf_fast(pg), og = sigf(po);
            float c = fmaf(fg, c2s0, ig * gg); c2s0 = c;
            float hA = og * tanhf_fast(c);

            pi = a01 + bB0;
            pf = a11 + bB1;
            pg = a21 + bB2;
            po = a31 + bB3;
            ig = sigf(pi); fg = sigf(pf); gg = tanhf_fast(pg); og = sigf(po);
            c = fmaf(fg, c2s1, ig * gg); c2s1 = c;
            float hB = og * tanhf_fast(c);

            uint32_t offA = (uint32_t)((OFF_H2 + (pbuf * NB + b0) * HD + gu) * 4);
            uint32_t offB = offA + HD * 4;
#pragma unroll
            for (int r = 0; r < CLN; r++) {
                asm volatile("st.shared::cluster.f32 [%0], %1;" :: "r"(peer[r] + offA), "f"(hA) : "memory");
                asm volatile("st.shared::cluster.f32 [%0], %1;" :: "r"(peer[r] + offB), "f"(hB) : "memory");
            }
        }
        cluster_bar();   // h2[pbuf] complete cluster-wide

        // ---------- output head: each CTA emits 4 of the 16 cluster batches ----------
        {
            const int warp = tid >> 5;
            if (warp < 4) {
                const int ob = ((int)rank << 2) + warp;   // local batch 0..15
                const float* __restrict__ h2p = sm + OFF_H2 + (pbuf * NB + ob) * HD;
                const float* __restrict__ wl  = sm + OFF_WLIN;
                float s = h2p[u] * wl[u]
                        + h2p[u + 32] * wl[u + 32]
                        + h2p[u + 64] * wl[u + 64]
                        + h2p[u + 96] * wl[u + 96];
                s += __shfl_xor_sync(0xffffffffu, s, 16);
                s += __shfl_xor_sync(0xffffffffu, s, 8);
                s += __shfl_xor_sync(0xffffffffu, s, 4);
                s += __shfl_xor_sync(0xffffffffu, s, 2);
                s += __shfl_xor_sync(0xffffffffu, s, 1);
                if (u == 0)
                    out[(size_t)(batch0 + ob) * LL + t] = s + blin;
            }
        }
    }
}

extern "C" void kernel_launch(void* const* d_in, const int* in_sizes, int n_in,
                              void* d_out, int out_size)
{
    (void)in_sizes; (void)n_in; (void)out_size;
    cudaFuncSetAttribute(lstm_persistent_kernel,
                         cudaFuncAttributeMaxDynamicSharedMemorySize, SMEM_BYTES);
    lstm_persistent_kernel<<<(BBZ / NB) * CLN, NTHREADS, SMEM_BYTES>>>(
        (const float*)d_in[0],   // x
        (const float*)d_in[1],   // w_ih1
        (const float*)d_in[2],   // w_hh1
        (const float*)d_in[3],   // b_ih1
        (const float*)d_in[4],   // b_hh1
        (const float*)d_in[5],   // w_ih2
        (const float*)d_in[6],   // w_hh2
        (const float*)d_in[7],   // b_ih2
        (const float*)d_in[8],   // b_hh2
        (const float*)d_in[9],   // w_lin
        (const float*)d_in[10],  // b_lin
        (float*)d_out);
}

// round 6
// speedup vs baseline: 1.2038x; 1.2038x over previous
#include <cuda_runtime.h>
#include <cstdint>

// Problem constants
#define HD  128     // hidden size
#define BBZ 512     // batch
#define LL  1000    // sequence length
#define NB  16      // batch rows per cluster
#define CLN 4       // CTAs per cluster
#define NTHREADS 256
#define KSTR 130    // weight row stride in floats (2 mod 32 -> conflict-free LDS.64)
#define GSTB (32 * KSTR * 4)   // gate stride in bytes within a weight matrix

// Shared memory layout (float offsets).
// Weights: [gate 0..3][unit 0..31][k 0..127], row stride KSTR.
// h buffers: [buf 0..1][batch 0..15][k 0..127] (k contiguous).
#define OFF_W1 0
#define OFF_W2 16640
#define OFF_W3 33280
#define OFF_H1 49920            // 2*16*128 = 4096 floats
#define OFF_H2 54016            // 2*16*128 = 4096 floats
#define SMEM_FLOATS 58112
#define SMEM_BYTES (SMEM_FLOATS * 4)   // 232448 B == smem opt-in cap

typedef unsigned long long u64t;

__device__ __forceinline__ float sigf(float v) {
    return __fdividef(1.f, 1.f + __expf(-v));
}
__device__ __forceinline__ float tanhf_fast(float v) {
    float a = fabsf(v);
    float e = __expf(-2.f * a);
    float r = __fdividef(1.f - e, 1.f + e);
    return copysignf(r, v);
}
__device__ __forceinline__ void cluster_bar() {
    asm volatile("barrier.cluster.arrive.aligned;" ::: "memory");
    asm volatile("barrier.cluster.wait.aligned;" ::: "memory");
}
__device__ __forceinline__ u64t lds64(uint32_t a) {
    u64t v; asm("ld.shared.b64 %0, [%1];" : "=l"(v) : "r"(a)); return v;
}
__device__ __forceinline__ void lds128x2(u64t& v0, u64t& v1, uint32_t a) {
    asm("ld.shared.v2.b64 {%0, %1}, [%2];" : "=l"(v0), "=l"(v1) : "r"(a));
}
__device__ __forceinline__ float lds32f(uint32_t a) {
    float v; asm("ld.shared.f32 %0, [%1];" : "=f"(v) : "r"(a)); return v;
}
__device__ __forceinline__ void sts32f(uint32_t a, float v) {
    asm volatile("st.shared.f32 [%0], %1;" :: "r"(a), "f"(v) : "memory");
}
__device__ __forceinline__ void ffma2(u64t& d, u64t a, u64t b) {
    asm("fma.rn.f32x2 %0, %1, %2, %0;" : "+l"(d) : "l"(a), "l"(b));
}
__device__ __forceinline__ float hadd2(u64t d) {
    float lo, hi;
    asm("mov.b64 {%0, %1}, %2;" : "=f"(lo), "=f"(hi) : "l"(d));
    return lo + hi;
}
__device__ __forceinline__ void pair_bar(int id) {
    asm volatile("bar.sync %0, 64;" :: "r"(id) : "memory");
}
__device__ __forceinline__ void st_cluster(uint32_t a, float v) {
    asm volatile("st.shared::cluster.f32 [%0], %1;" :: "r"(a), "f"(v) : "memory");
}

__global__ void __launch_bounds__(NTHREADS, 1) __cluster_dims__(CLN, 1, 1)
lstm_persistent_kernel(const float* __restrict__ x,
                       const float* __restrict__ w_ih1,
                       const float* __restrict__ w_hh1,
                       const float* __restrict__ b_ih1,
                       const float* __restrict__ b_hh1,
                       const float* __restrict__ w_ih2,
                       const float* __restrict__ w_hh2,
                       const float* __restrict__ b_ih2,
                       const float* __restrict__ b_hh2,
                       const float* __restrict__ w_lin,
                       const float* __restrict__ b_lin,
                       float* __restrict__ out)
{
    extern __shared__ float sm[];
    const int tid = threadIdx.x;
    uint32_t rank;
    asm("mov.u32 %0, %%cluster_ctarank;" : "=r"(rank));
    const int cid = blockIdx.x / CLN;
    const int batch0 = cid * NB;

    // ---- init: weight slices into smem, row-major per (gate,unit) ----
    for (int idx = tid; idx < 4 * 32 * HD; idx += NTHREADS) {
        int g = idx >> 12;
        int u5 = (idx >> 7) & 31;
        int k = idx & 127;
        int R = g * HD + (int)rank * 32 + u5;
        int o = (g * 32 + u5) * KSTR + k;
        sm[OFF_W1 + o] = w_hh1[R * HD + k];
        sm[OFF_W2 + o] = w_ih2[R * HD + k];
        sm[OFF_W3 + o] = w_hh2[R * HD + k];
    }
    for (int idx = tid; idx < 4096; idx += NTHREADS) {
        sm[OFF_H1 + idx] = 0.f;
        sm[OFF_H2 + idx] = 0.f;
    }

    // ---- per-thread assignment ----
    const int u  = tid & 31;          // hidden unit lane
    const int w  = tid >> 5;          // warp 0..7
    const int bg = w & 3;             // batch group (4 batches)
    const int ks = w >> 2;            // k-half: 0 -> k[0,64), 1 -> k[64,128)
    const int b0 = bg * 4;            // local batch base
    const int ob0 = b0 + 2 * ks;      // first OWNED local batch (2 owned)
    const int gu = (int)rank * 32 + u;
    const int kbase = ks * 64;

    // per-lane constants from gmem
    const float wi0 = w_ih1[0 * HD + gu], wi1 = w_ih1[1 * HD + gu];
    const float wi2 = w_ih1[2 * HD + gu], wi3 = w_ih1[3 * HD + gu];
    const float bA0 = b_ih1[0 * HD + gu] + b_hh1[0 * HD + gu];
    const float bA1 = b_ih1[1 * HD + gu] + b_hh1[1 * HD + gu];
    const float bA2 = b_ih1[2 * HD + gu] + b_hh1[2 * HD + gu];
    const float bA3 = b_ih1[3 * HD + gu] + b_hh1[3 * HD + gu];
    const float bB0 = b_ih2[0 * HD + gu] + b_hh2[0 * HD + gu];
    const float bB1 = b_ih2[1 * HD + gu] + b_hh2[1 * HD + gu];
    const float bB2 = b_ih2[2 * HD + gu] + b_hh2[2 * HD + gu];
    const float bB3 = b_ih2[3 * HD + gu] + b_hh2[3 * HD + gu];
    const float wl0 = w_lin[u], wl1 = w_lin[u + 32];
    const float wl2 = w_lin[u + 64], wl3 = w_lin[u + 96];
    const float blin = b_lin[0];

    float c1[2] = {0.f, 0.f};
    float c2[2] = {0.f, 0.f};

    const uint32_t sbase = (uint32_t)__cvta_generic_to_shared(sm);
    uint32_t peer[CLN];
#pragma unroll
    for (int r = 0; r < CLN; r++)
        asm("mapa.shared::cluster.u32 %0, %1, %2;" : "=r"(peer[r]) : "r"(sbase), "r"(r));

    // fixed per-thread addresses (bytes)
    const uint32_t w1base = sbase + (OFF_W1 + u * KSTR + kbase) * 4;
    const uint32_t w2base = sbase + (OFF_W2 + u * KSTR + kbase) * 4;
    const uint32_t w3base = sbase + (OFF_W3 + u * KSTR + kbase) * 4;
    const size_t xrow0 = (size_t)(batch0 + ob0) * LL;
    const size_t xrow1 = xrow0 + LL;

    cluster_bar();   // weights + zeroed h visible cluster-wide

    for (int t = 0; t < LL; ++t) {
        const int pbuf = t & 1, qbuf = pbuf ^ 1;

        // x for the 2 owned batches (LDG early; consumed in epilogue)
        const float xv0 = x[xrow0 + t];
        const float xv1 = x[xrow1 + t];

        // ================= layer 1 matvec: Whh1 @ h1[qbuf] over k-half =========
        u64t acc[4][4];
#pragma unroll
        for (int g = 0; g < 4; g++)
#pragma unroll
            for (int b = 0; b < 4; b++) acc[g][b] = 0ULL;
        {
            const uint32_t hqb = sbase + (OFF_H1 + qbuf * 2048 + b0 * 128 + kbase) * 4;
#pragma unroll 4
            for (int i = 0; i < 16; ++i) {
                const uint32_t wo = w1base + i * 16;
                u64t wp[4][2];
#pragma unroll
                for (int g = 0; g < 4; g++) {
                    wp[g][0] = lds64(wo + g * GSTB);
                    wp[g][1] = lds64(wo + g * GSTB + 8);
                }
#pragma unroll
                for (int b = 0; b < 4; b++) {
                    u64t h0, h1v;
                    lds128x2(h0, h1v, hqb + b * 512 + i * 16);
#pragma unroll
                    for (int g = 0; g < 4; g++) {
                        ffma2(acc[g][b], wp[g][0], h0);
                        ffma2(acc[g][b], wp[g][1], h1v);
                    }
                }
            }
        }
        // ---- k-reduction exchange (scratch = dead region h2[pbuf]) ----
        float s[4][4];
#pragma unroll
        for (int g = 0; g < 4; g++)
#pragma unroll
            for (int b = 0; b < 4; b++) s[g][b] = hadd2(acc[g][b]);
        {
            const uint32_t scr = sbase + (OFF_H2 + pbuf * 2048) * 4;
#pragma unroll
            for (int j = 0; j < 2; j++) {
                const int bl = (ks ^ 1) * 2 + j;    // non-owned local batch
#pragma unroll
                for (int g = 0; g < 4; g++)
                    sts32f(scr + ((((w * 2 + j) * 4 + g) * 32 + u) << 2), s[g][bl]);
            }
            pair_bar(bg + 1);
#pragma unroll
            for (int j = 0; j < 2; j++) {
                const int bl = ks * 2 + j;          // owned local batch
#pragma unroll
                for (int g = 0; g < 4; g++)
                    s[g][bl] += lds32f(scr + (((((w ^ 4) * 2 + j) * 4 + g) * 32 + u) << 2));
            }
        }
        // ---- layer-1 cell for 2 owned batches + cluster broadcast of h1 ----
        {
#pragma unroll
            for (int j = 0; j < 2; j++) {
                const int bl = ks * 2 + j;
                const float xv = j ? xv1 : xv0;
                float pi = fmaf(xv, wi0, s[0][bl]) + bA0;
                float pf = fmaf(xv, wi1, s[1][bl]) + bA1;
                float pg = fmaf(xv, wi2, s[2][bl]) + bA2;
                float po = fmaf(xv, wi3, s[3][bl]) + bA3;
                float ig = sigf(pi), fg = sigf(pf), gg = tanhf_fast(pg), og = sigf(po);
                float c = fmaf(fg, c1[j], ig * gg);
                c1[j] = c;
                float h = og * tanhf_fast(c);
                const uint32_t off = (uint32_t)((OFF_H1 + (pbuf * NB + ob0 + j) * 128 + gu) * 4);
#pragma unroll
                for (int r = 0; r < CLN; r++) st_cluster(peer[r] + off, h);
            }
        }
        cluster_bar();   // h1[pbuf] complete cluster-wide

        // ================= layer 2 matvec: Wih2@h1[pbuf] + Whh2@h2[qbuf] =========
#pragma unroll
        for (int g = 0; g < 4; g++)
#pragma unroll
            for (int b = 0; b < 4; b++) acc[g][b] = 0ULL;
        {
            const uint32_t h1p = sbase + (OFF_H1 + pbuf * 2048 + b0 * 128 + kbase) * 4;
            const uint32_t h2q = sbase + (OFF_H2 + qbuf * 2048 + b0 * 128 + kbase) * 4;
#pragma unroll 2
            for (int i = 0; i < 16; ++i) {
                const uint32_t wo2 = w2base + i * 16;
                const uint32_t wo3 = w3base + i * 16;
                u64t wp2[4][2], wp3[4][2];
#pragma unroll
                for (int g = 0; g < 4; g++) {
                    wp2[g][0] = lds64(wo2 + g * GSTB);
                    wp2[g][1] = lds64(wo2 + g * GSTB + 8);
                    wp3[g][0] = lds64(wo3 + g * GSTB);
                    wp3[g][1] = lds64(wo3 + g * GSTB + 8);
                }
#pragma unroll
                for (int b = 0; b < 4; b++) {
                    u64t p0, p1, q0, q1;
                    lds128x2(p0, p1, h1p + b * 512 + i * 16);
                    lds128x2(q0, q1, h2q + b * 512 + i * 16);
#pragma unroll
                    for (int g = 0; g < 4; g++) {
                        ffma2(acc[g][b], wp2[g][0], p0);
                        ffma2(acc[g][b], wp2[g][1], p1);
                        ffma2(acc[g][b], wp3[g][0], q0);
                        ffma2(acc[g][b], wp3[g][1], q1);
                    }
                }
            }
        }
        // ---- k-reduction exchange (scratch = dead region h1[qbuf]) ----
#pragma unroll
        for (int g = 0; g < 4; g++)
#pragma unroll
            for (int b = 0; b < 4; b++) s[g][b] = hadd2(acc[g][b]);
        {
            const uint32_t scr = sbase + (OFF_H1 + qbuf * 2048) * 4;
#pragma unroll
            for (int j = 0; j < 2; j++) {
                const int bl = (ks ^ 1) * 2 + j;
#pragma unroll
                for (int g = 0; g < 4; g++)
                    sts32f(scr + ((((w * 2 + j) * 4 + g) * 32 + u) << 2), s[g][bl]);
            }
            pair_bar(bg + 1);
#pragma unroll
            for (int j = 0; j < 2; j++) {
                const int bl = ks * 2 + j;
#pragma unroll
                for (int g = 0; g < 4; g++)
                    s[g][bl] += lds32f(scr + (((((w ^ 4) * 2 + j) * 4 + g) * 32 + u) << 2));
            }
        }
        // ---- layer-2 cell for 2 owned batches + cluster broadcast of h2 ----
        {
#pragma unroll
            for (int j = 0; j < 2; j++) {
                const int bl = ks * 2 + j;
                float pi = s[0][bl] + bB0;
                float pf = s[1][bl] + bB1;
                float pg = s[2][bl] + bB2;
                float po = s[3][bl] + bB3;
                float ig = sigf(pi), fg = sigf(pf), gg = tanhf_fast(pg), og = sigf(po);
                float c = fmaf(fg, c2[j], ig * gg);
                c2[j] = c;
                float h = og * tanhf_fast(c);
                const uint32_t off = (uint32_t)((OFF_H2 + (pbuf * NB + ob0 + j) * 128 + gu) * 4);
#pragma unroll
                for (int r = 0; r < CLN; r++) st_cluster(peer[r] + off, h);
            }
        }
        cluster_bar();   // h2[pbuf] complete cluster-wide

        // ---------- output head: each warp emits its 2 owned batches ----------
        {
            const float* __restrict__ hpA = sm + OFF_H2 + pbuf * 2048 + (ob0) * 128;
            const float* __restrict__ hpB = hpA + 128;
            float d0 = hpA[u] * wl0 + hpA[u + 32] * wl1 + hpA[u + 64] * wl2 + hpA[u + 96] * wl3;
            float d1 = hpB[u] * wl0 + hpB[u + 32] * wl1 + hpB[u + 64] * wl2 + hpB[u + 96] * wl3;
#pragma unroll
            for (int m = 16; m >= 1; m >>= 1) {
                d0 += __shfl_xor_sync(0xffffffffu, d0, m);
                d1 += __shfl_xor_sync(0xffffffffu, d1, m);
            }
            if (u == 0) {
                out[xrow0 + t] = d0 + blin;
                out[xrow1 + t] = d1 + blin;
            }
        }
    }
}

extern "C" void kernel_launch(void* const* d_in, const int* in_sizes, int n_in,
                              void* d_out, int out_size)
{
    (void)in_sizes; (void)n_in; (void)out_size;
    cudaFuncSetAttribute(lstm_persistent_kernel,
                         cudaFuncAttributeMaxDynamicSharedMemorySize, SMEM_BYTES);
    lstm_persistent_kernel<<<(BBZ / NB) * CLN, NTHREADS, SMEM_BYTES>>>(
        (const float*)d_in[0],   // x
        (const float*)d_in[1],   // w_ih1
        (const float*)d_in[2],   // w_hh1
        (const float*)d_in[3],   // b_ih1
        (const float*)d_in[4],   // b_hh1
        (const float*)d_in[5],   // w_ih2
        (const float*)d_in[6],   // w_hh2
        (const float*)d_in[7],   // b_ih2
        (const float*)d_in[8],   // b_hh2
        (const float*)d_in[9],   // w_lin
        (const float*)d_in[10],  // b_lin
        (float*)d_out);
}